// round 1
// baseline (speedup 1.0000x reference)
#include <cuda_runtime.h>

#define N_NODES 50000
#define N_EDGES 1000000
#define D_IN    64
#define D_HID   64
#define D_OUTF  32

// ---- scratch (no allocs allowed) ----
__device__ float g_deg [N_NODES];
__device__ float g_dinv[N_NODES];
__device__ float g_h   [N_NODES * D_HID];   // h1s (layer1), reused as h2s (layer2, first N*32)
__device__ float g_agg [N_NODES * D_HID];   // agg1 -> out1 (in place)

__device__ __forceinline__ void red_add_v4(float* p, float4 v) {
    asm volatile("red.global.add.v4.f32 [%0], {%1, %2, %3, %4};"
                 :: "l"(p), "f"(v.x), "f"(v.y), "f"(v.z), "f"(v.w) : "memory");
}

// ---------------- degree / norm ----------------
__global__ void k_deg_init() {
    int i = blockIdx.x * blockDim.x + threadIdx.x;
    if (i < N_NODES) g_deg[i] = 1.0f;   // self-loop weight
}

__global__ void k_deg_count(const int* __restrict__ dst, const float* __restrict__ w) {
    int e = blockIdx.x * blockDim.x + threadIdx.x;
    if (e < N_EDGES) atomicAdd(&g_deg[dst[e]], w[e]);
}

__global__ void k_dinv() {
    int i = blockIdx.x * blockDim.x + threadIdx.x;
    if (i < N_NODES) g_dinv[i] = rsqrtf(g_deg[i]);   // deg >= 1 always
}

// ---------------- GEMM + dinv scale, writes hs and initializes agg with hs (self loop) ----
// LAYER==1: X = param x,    H = g_h (N*64), AGG = g_agg (N*64)
// LAYER==2: X = g_agg(out1),H = g_h (N*32), AGG = d_out (N*32)
template <int DI, int DO, int LAYER>
__global__ void k_gemm_scale(const float* __restrict__ Xparam,
                             const float* __restrict__ W,
                             float* __restrict__ aggParam) {
    constexpr int ROWS = 256 / DO;
    __shared__ float Ws[DI * DO];
    __shared__ float xs[ROWS][DI];

    const float* X   = (LAYER == 1) ? Xparam : g_agg;
    float*       H   = g_h;
    float*       AGG = (LAYER == 1) ? g_agg : aggParam;

    for (int i = threadIdx.x; i < DI * DO; i += 256) Ws[i] = W[i];

    int lr  = threadIdx.x / DO;
    int col = threadIdx.x % DO;
    int row = blockIdx.x * ROWS + lr;

    for (int i = threadIdx.x; i < ROWS * DI; i += 256) {
        int r = i / DI, c = i % DI;
        int gr = blockIdx.x * ROWS + r;
        xs[r][c] = (gr < N_NODES) ? X[gr * DI + c] : 0.0f;
    }
    __syncthreads();
    if (row >= N_NODES) return;

    float acc = 0.0f;
#pragma unroll
    for (int k = 0; k < DI; k++)
        acc += xs[lr][k] * Ws[k * DO + col];

    float v = g_dinv[row] * acc;
    H  [row * DO + col] = v;
    AGG[row * DO + col] = v;   // self-loop contribution
}

// ---------------- edge scatter: AGG[dst] += w * H[src], vectorized reds ----
// LAYER==1: H=g_h (stride 64), AGG=g_agg. LAYER==2: H=g_h (stride 32), AGG=d_out.
template <int D, int LAYER>
__global__ void k_scatter(const int* __restrict__ src,
                          const int* __restrict__ dst,
                          const float* __restrict__ w,
                          float* __restrict__ aggParam) {
    constexpr int TPE = D / 4;   // threads per edge
    int tid = blockIdx.x * blockDim.x + threadIdx.x;
    int e = tid / TPE;
    int p = tid % TPE;
    if (e >= N_EDGES) return;

    const float* H   = g_h;
    float*       AGG = (LAYER == 1) ? g_agg : aggParam;

    int   s  = __ldg(&src[e]);
    int   d  = __ldg(&dst[e]);
    float we = __ldg(&w[e]);

    float4 hv = *reinterpret_cast<const float4*>(H + s * D + p * 4);
    float4 m  = make_float4(we * hv.x, we * hv.y, we * hv.z, we * hv.w);
    red_add_v4(AGG + d * D + p * 4, m);
}

// ---------------- finalize: A = relu(dinv*A + b), in place ----
template <int D, int LAYER>
__global__ void k_final(float* __restrict__ aggParam, const float* __restrict__ b) {
    int i = blockIdx.x * blockDim.x + threadIdx.x;
    if (i >= N_NODES * D) return;
    float* A = (LAYER == 1) ? g_agg : aggParam;
    int row = i / D, col = i % D;
    float v = g_dinv[row] * A[i] + b[col];
    A[i] = fmaxf(v, 0.0f);
}

extern "C" void kernel_launch(void* const* d_in, const int* in_sizes, int n_in,
                              void* d_out, int out_size) {
    const float* x   = (const float*)d_in[0];
    const int*   ei  = (const int*)  d_in[1];   // [2, E]
    const float* ew  = (const float*)d_in[2];
    const float* W1  = (const float*)d_in[3];
    const float* b1  = (const float*)d_in[4];
    const float* W2  = (const float*)d_in[5];
    const float* b2  = (const float*)d_in[6];
    float*       out = (float*)d_out;

    const int* src = ei;
    const int* dst = ei + N_EDGES;

    // degrees + norm
    k_deg_init <<<(N_NODES + 255) / 256, 256>>>();
    k_deg_count<<<(N_EDGES + 255) / 256, 256>>>(dst, ew);
    k_dinv     <<<(N_NODES + 255) / 256, 256>>>();

    // ---- layer 1 ----
    {
        constexpr int ROWS = 256 / D_HID;
        k_gemm_scale<D_IN, D_HID, 1><<<(N_NODES + ROWS - 1) / ROWS, 256>>>(x, W1, nullptr);
        int nthr = N_EDGES * (D_HID / 4);
        k_scatter<D_HID, 1><<<(nthr + 255) / 256, 256>>>(src, dst, ew, nullptr);
        k_final<D_HID, 1><<<(N_NODES * D_HID + 255) / 256, 256>>>(nullptr, b1);
    }

    // ---- layer 2 ----
    {
        constexpr int ROWS = 256 / D_OUTF;
        k_gemm_scale<D_HID, D_OUTF, 2><<<(N_NODES + ROWS - 1) / ROWS, 256>>>(nullptr, W2, out);
        int nthr = N_EDGES * (D_OUTF / 4);
        k_scatter<D_OUTF, 2><<<(nthr + 255) / 256, 256>>>(src, dst, ew, out);
        k_final<D_OUTF, 2><<<(N_NODES * D_OUTF + 255) / 256, 256>>>(out, b2);
    }
}

// round 2
// speedup vs baseline: 1.3890x; 1.3890x over previous
#include <cuda_runtime.h>

#define N_NODES 50000
#define N_EDGES 1000000
#define D_IN    64
#define D_HID   64
#define D_OUTF  32

// ---- scratch (no allocs allowed) ----
__device__ float g_deg [N_NODES];
__device__ float g_dinv[N_NODES];
__device__ float g_h   [N_NODES * D_HID];   // hs (pre-scaled by dinv)
__device__ float g_agg [N_NODES * D_HID];   // layer1 aggregation -> out1 in place

__device__ __forceinline__ void red_add_v4(float* p, float4 v) {
    asm volatile("red.global.add.v4.f32 [%0], {%1, %2, %3, %4};"
                 :: "l"(p), "f"(v.x), "f"(v.y), "f"(v.z), "f"(v.w) : "memory");
}

// ---------------- degree / norm ----------------
__global__ void k_deg_init() {
    int i = blockIdx.x * blockDim.x + threadIdx.x;
    if (i < N_NODES) g_deg[i] = 1.0f;   // self-loop weight
}

__global__ void k_deg_count(const int* __restrict__ dst, const float* __restrict__ w) {
    int e = blockIdx.x * blockDim.x + threadIdx.x;
    if (e < N_EDGES) atomicAdd(&g_deg[dst[e]], w[e]);
}

__global__ void k_dinv() {
    int i = blockIdx.x * blockDim.x + threadIdx.x;
    if (i < N_NODES) g_dinv[i] = rsqrtf(g_deg[i]);
}

// ---------------- register-blocked GEMM + dinv scale ----------------
// DI = 64 always. Each thread computes a 4x4 tile via outer products.
// Writes hs = dinv*(X@W) to H, and also to AGG (self-loop init).
// LAYER==1: X=x param, AGG=g_agg.  LAYER==2: X=g_agg(out1), AGG=d_out.
template <int DO, int LAYER>
__global__ __launch_bounds__(256) void k_gemm_scale(
        const float* __restrict__ Xparam,
        const float* __restrict__ W,
        float* __restrict__ aggParam) {
    constexpr int DI   = 64;
    constexpr int TX   = DO / 4;          // thread-col groups (16 or 8)
    constexpr int TYN  = 256 / TX;        // thread-row groups (16 or 32)
    constexpr int ROWS = TYN * 4;         // block row tile (64 or 128)
    constexpr int XS   = ROWS + 4;        // padded stride, %4==0 (float4-aligned)

    __shared__ float Ws[DI * DO];         // W[k][col]
    __shared__ float xsT[DI * XS];        // xT[k][row]

    const float* X   = (LAYER == 1) ? Xparam : g_agg;
    float*       AGG = (LAYER == 1) ? g_agg : aggParam;

    const int tid = threadIdx.x;
    const int tx  = tid % TX;             // col group
    const int ty  = tid / TX;             // row group
    const int blockRow = blockIdx.x * ROWS;

    // load W (coalesced float4)
    for (int i = tid; i < DI * DO / 4; i += 256)
        reinterpret_cast<float4*>(Ws)[i] =
            reinterpret_cast<const float4*>(W)[i];

    // load X tile transposed: xsT[k][row] = X[blockRow+row][k]
    for (int i = tid; i < ROWS * (DI / 4); i += 256) {
        int row = i / (DI / 4);
        int c4  = i % (DI / 4);
        int gr  = blockRow + row;
        float4 v = make_float4(0.f, 0.f, 0.f, 0.f);
        if (gr < N_NODES)
            v = reinterpret_cast<const float4*>(X + gr * DI)[c4];
        xsT[(c4 * 4 + 0) * XS + row] = v.x;
        xsT[(c4 * 4 + 1) * XS + row] = v.y;
        xsT[(c4 * 4 + 2) * XS + row] = v.z;
        xsT[(c4 * 4 + 3) * XS + row] = v.w;
    }
    __syncthreads();

    float acc[4][4];
#pragma unroll
    for (int i = 0; i < 4; i++)
#pragma unroll
        for (int j = 0; j < 4; j++) acc[i][j] = 0.0f;

#pragma unroll
    for (int k = 0; k < DI; k++) {
        float4 a = *reinterpret_cast<const float4*>(&xsT[k * XS + ty * 4]);
        float4 b = *reinterpret_cast<const float4*>(&Ws [k * DO + tx * 4]);
        acc[0][0] += a.x * b.x; acc[0][1] += a.x * b.y; acc[0][2] += a.x * b.z; acc[0][3] += a.x * b.w;
        acc[1][0] += a.y * b.x; acc[1][1] += a.y * b.y; acc[1][2] += a.y * b.z; acc[1][3] += a.y * b.w;
        acc[2][0] += a.z * b.x; acc[2][1] += a.z * b.y; acc[2][2] += a.z * b.z; acc[2][3] += a.z * b.w;
        acc[3][0] += a.w * b.x; acc[3][1] += a.w * b.y; acc[3][2] += a.w * b.z; acc[3][3] += a.w * b.w;
    }

#pragma unroll
    for (int i = 0; i < 4; i++) {
        int row = blockRow + ty * 4 + i;
        if (row >= N_NODES) break;
        float dv = g_dinv[row];
        float4 v = make_float4(dv * acc[i][0], dv * acc[i][1],
                               dv * acc[i][2], dv * acc[i][3]);
        *reinterpret_cast<float4*>(&g_h[row * DO + tx * 4]) = v;
        *reinterpret_cast<float4*>(&AGG[row * DO + tx * 4]) = v;
    }
}

// ---------------- edge scatter: AGG[dst] += w * H[src], vectorized reds ----
template <int D, int LAYER>
__global__ void k_scatter(const int* __restrict__ src,
                          const int* __restrict__ dst,
                          const float* __restrict__ w,
                          float* __restrict__ aggParam) {
    constexpr int TPE = D / 4;   // threads per edge
    int tid = blockIdx.x * blockDim.x + threadIdx.x;
    int e = tid / TPE;
    int p = tid % TPE;
    if (e >= N_EDGES) return;

    const float* H   = g_h;
    float*       AGG = (LAYER == 1) ? g_agg : aggParam;

    int   s  = __ldg(&src[e]);
    int   d  = __ldg(&dst[e]);
    float we = __ldg(&w[e]);

    float4 hv = *reinterpret_cast<const float4*>(H + s * D + p * 4);
    float4 m  = make_float4(we * hv.x, we * hv.y, we * hv.z, we * hv.w);
    red_add_v4(AGG + d * D + p * 4, m);
}

// ---------------- finalize: A = relu(dinv*A + b), in place ----
template <int D, int LAYER>
__global__ void k_final(float* __restrict__ aggParam, const float* __restrict__ b) {
    int i = blockIdx.x * blockDim.x + threadIdx.x;
    if (i >= N_NODES * D) return;
    float* A = (LAYER == 1) ? g_agg : aggParam;
    int row = i / D, col = i % D;
    float v = g_dinv[row] * A[i] + b[col];
    A[i] = fmaxf(v, 0.0f);
}

extern "C" void kernel_launch(void* const* d_in, const int* in_sizes, int n_in,
                              void* d_out, int out_size) {
    const float* x   = (const float*)d_in[0];
    const int*   ei  = (const int*)  d_in[1];   // [2, E]
    const float* ew  = (const float*)d_in[2];
    const float* W1  = (const float*)d_in[3];
    const float* b1  = (const float*)d_in[4];
    const float* W2  = (const float*)d_in[5];
    const float* b2  = (const float*)d_in[6];
    float*       out = (float*)d_out;

    const int* src = ei;
    const int* dst = ei + N_EDGES;

    // degrees + norm
    k_deg_init <<<(N_NODES + 255) / 256, 256>>>();
    k_deg_count<<<(N_EDGES + 255) / 256, 256>>>(dst, ew);
    k_dinv     <<<(N_NODES + 255) / 256, 256>>>();

    // ---- layer 1 ----
    {
        constexpr int ROWS = (256 / (D_HID / 4)) * 4;   // 64
        k_gemm_scale<D_HID, 1><<<(N_NODES + ROWS - 1) / ROWS, 256>>>(x, W1, nullptr);
        int nthr = N_EDGES * (D_HID / 4);
        k_scatter<D_HID, 1><<<(nthr + 255) / 256, 256>>>(src, dst, ew, nullptr);
        k_final<D_HID, 1><<<(N_NODES * D_HID + 255) / 256, 256>>>(nullptr, b1);
    }

    // ---- layer 2 ----
    {
        constexpr int ROWS = (256 / (D_OUTF / 4)) * 4;  // 128
        k_gemm_scale<D_OUTF, 2><<<(N_NODES + ROWS - 1) / ROWS, 256>>>(nullptr, W2, out);
        int nthr = N_EDGES * (D_OUTF / 4);
        k_scatter<D_OUTF, 2><<<(nthr + 255) / 256, 256>>>(src, dst, ew, out);
        k_final<D_OUTF, 2><<<(N_NODES * D_OUTF + 255) / 256, 256>>>(out, b2);
    }
}